// round 13
// baseline (speedup 1.0000x reference)
#include <cuda_runtime.h>
#include <math.h>

#define HDIM 512
#define NN2 32
#define LEN 2048
#define MM 1025
#define KF_STRIDE 1028

// bank-conflict padding for FFT buffers: bijective, strictly increasing
#define P(i) ((i) + ((i) >> 3))
#define FFT_BUF 1160

__device__ float2 g_kf[HDIM * KF_STRIDE];

__device__ __forceinline__ float2 cmul(float2 w, float2 y) {
    return make_float2(w.x*y.x - w.y*y.y, w.x*y.y + w.y*y.x);
}

// Woodbury + bilinear post-factor for one m (r_ab already include dt)
__device__ __forceinline__ float2 wood(float R0, float I0, float R1, float I1,
                                       float R2, float I2, float R3, float I3,
                                       float t) {
    const float dr = 1.0f + R3, di = I3;
    const float idn = __fdividef(1.0f, dr*dr + di*di);
    const float numr = R1*R2 - I1*I2;
    const float numi = R1*I2 + I1*R2;
    const float cr = (numr*dr + numi*di) * idn;
    const float ci = (numi*dr - numr*di) * idn;
    const float kfr = R0 - cr, kfi = I0 - ci;
    return make_float2(kfr - kfi*t, kfi + kfr*t);   // * (1 + i t)
}

// Full Cauchy + Woodbury chain for ONE m (scalar).
// Summand per n (conj pair fused):  (b + i a t)/(e + i f),
//   e = c - 4t^2, f = d*t, c = |w|^2, d = -4 wr, a = 4 Re v, b = -2 Re(v w*)
__device__ __forceinline__ float2 cauchy_m(
    const float4* __restrict__ sc0,   // (c, d, a0, b0)
    const float4* __restrict__ sc1,   // (a1, b1, a2, b2)
    const float4* __restrict__ sc2,   // (a3, b3, -, -)
    float t)
{
    const float T2n = -4.0f * t * t;

    float R0 = 0.f, I0 = 0.f, R1 = 0.f, I1 = 0.f;
    float R2 = 0.f, I2 = 0.f, R3 = 0.f, I3 = 0.f;

    #pragma unroll 2
    for (int n = 0; n < NN2; n++) {
        const float4 k0 = sc0[n];
        const float4 k1 = sc1[n];
        const float4 k2 = sc2[n];

        const float e   = k0.x + T2n;
        const float f   = k0.y * t;
        const float mag = fmaf(e, e, f * f);
        const float r   = __fdividef(1.0f, mag);
        const float er  = e * r;
        const float fr  = f * r;
        const float ter = t * er;
        const float tfr = t * fr;

        // Re += b*er + a*tfr ; Im += a*ter - b*fr
        R0 = fmaf(k0.w, er, fmaf(k0.z, tfr, R0));
        I0 = fmaf(k0.z, ter, fmaf(-k0.w, fr, I0));
        R1 = fmaf(k1.y, er, fmaf(k1.x, tfr, R1));
        I1 = fmaf(k1.x, ter, fmaf(-k1.y, fr, I1));
        R2 = fmaf(k1.w, er, fmaf(k1.z, tfr, R2));
        I2 = fmaf(k1.z, ter, fmaf(-k1.w, fr, I2));
        R3 = fmaf(k2.y, er, fmaf(k2.x, tfr, R3));
        I3 = fmaf(k2.x, ter, fmaf(-k2.y, fr, I3));
    }

    return wood(R0, I0, R1, I1, R2, I2, R3, I3, t);
}

// ---------------------------------------------------------------------------
// Stage 1: Cauchy + Woodbury. grid (512 h, 4 chunks) x 256 threads, one m per
// thread, scalar math, 5 CTAs/SM (40 warps/SM resident).
// ---------------------------------------------------------------------------
__global__ void __launch_bounds__(256, 5)
cauchy_kernel(const float* __restrict__ log_dt,
              const float* __restrict__ log_w_real,
              const float* __restrict__ w_imag,
              const float* __restrict__ Bmat,
              const float* __restrict__ Cmat,
              const float* __restrict__ Pmat)
{
    __shared__ float4 sc0[NN2];   // (c, d, a0, b0)
    __shared__ float4 sc1[NN2];   // (a1, b1, a2, b2)
    __shared__ float4 sc2[NN2];   // (a3, b3, 0, 0)

    const int h     = blockIdx.x;
    const int chunk = blockIdx.y;
    const int tid   = threadIdx.x;

    if (tid < NN2) {
        const int n   = tid;
        const int idx = h * NN2 + n;
        const float dt = expf(log_dt[h]);
        const float wr = -expf(log_w_real[idx]) * dt;
        const float wi = w_imag[idx] * dt;
        const float c  = wr*wr + wi*wi;
        const float d  = -4.0f * wr;

        const float Br = Bmat[2*idx], Bi = Bmat[2*idx+1];
        const float Cr = Cmat[2*idx], Ci = Cmat[2*idx+1];
        const float Pr = Pmat[2*idx], Pi = Pmat[2*idx+1];
        float vr[4], vi[4];
        vr[0] = Br*Cr - Bi*Ci;  vi[0] = Br*Ci + Bi*Cr;   // B*C
        vr[1] = Br*Pr + Bi*Pi;  vi[1] = Bi*Pr - Br*Pi;   // B*conj(P)
        vr[2] = Pr*Cr - Pi*Ci;  vi[2] = Pr*Ci + Pi*Cr;   // P*C
        vr[3] = Pr*Pr + Pi*Pi;  vi[3] = 0.0f;            // |P|^2

        float a[4], b[4];
        #pragma unroll
        for (int k = 0; k < 4; k++) {
            a[k] =  4.0f * dt * vr[k];
            b[k] = -2.0f * dt * (vr[k]*wr + vi[k]*wi);
        }
        sc0[n] = make_float4(c, d, a[0], b[0]);
        sc1[n] = make_float4(a[1], b[1], a[2], b[2]);
        sc2[n] = make_float4(a[3], b[3], 0.f, 0.f);
    }
    __syncthreads();

    const int m = tid + 256 * chunk;
    float s, c;
    sincospif((float)m * (1.0f/2048.0f), &s, &c);
    const float t = fminf(__fdividef(s, c), 1e8f);   // tan(pi m/L)

    g_kf[h * KF_STRIDE + m] = cauchy_m(sc0, sc1, sc2, t);

    // Nyquist m=1024 (t clamped -> converged asymptotic limit); whole warp 0
    // of chunk 0 computes redundantly (uniform, no divergence), lane 0 stores.
    if (chunk == 0 && tid < 32) {
        const float2 ny = cauchy_m(sc0, sc1, sc2, 1e8f);
        if (tid == 0) g_kf[h * KF_STRIDE + 1024] = ny;
    }
}

// ---------------------------------------------------------------------------
// Stage 2: irfft(2048) per h via real-packing + 1024-pt radix-4 Stockham,
// padded indexing, shared twiddle table. g_kf is L2-resident between kernels.
// ---------------------------------------------------------------------------
__global__ void __launch_bounds__(256, 8)
irfft_kernel(float* __restrict__ out)
{
    __shared__ float2 sA[FFT_BUF];
    __shared__ float2 sB[FFT_BUF];
    __shared__ float2 tw4[768];             // tw4[j] = e^{+2*pi*i*j/1024}

    const int h   = blockIdx.x;
    const int tid = threadIdx.x;
    const float2* __restrict__ K = &g_kf[h * KF_STRIDE];

    #pragma unroll
    for (int r = 0; r < 3; r++) {
        const int j = tid + r * 256;
        float s, c; sincospif((float)j * (1.0f/512.0f), &s, &c);
        tw4[j] = make_float2(c, s);
    }

    // Z'[m] = (E[m] + i*O[m]) / 1024  (real-packing of the c2r transform)
    #pragma unroll
    for (int r = 0; r < 4; r++) {
        const int m = tid + r * 256;
        float2 km = K[m];
        float2 kn = K[1024 - m];
        if (m == 0) { km.y = 0.f; kn.y = 0.f; }
        const float Ex = 0.5f * (km.x + kn.x);
        const float Ey = 0.5f * (km.y - kn.y);
        const float Ox = 0.5f * (km.x - kn.x);
        const float Oy = 0.5f * (km.y + kn.y);
        float s, c;
        sincospif((float)m * (1.0f / 1024.0f), &s, &c);
        const float Orx = Ox * c - Oy * s;
        const float Ory = Ox * s + Oy * c;
        const float scale = 1.0f / 1024.0f;
        sA[P(m)] = make_float2((Ex - Ory) * scale, (Ey + Orx) * scale);
    }

    // 5 radix-4 Stockham stages (self-sorting), inverse sign (+), P-indexed.
    float2* src = sA;
    float2* dst = sB;
    int s_ = 1, ls = 0;
    #pragma unroll 1
    for (int ncur = 1024; ncur >= 4; ncur >>= 2) {
        __syncthreads();
        const int mq = ncur >> 2;
        const int q  = tid & (s_ - 1);
        const int p  = tid >> ls;
        const int rb = q + s_ * p;
        const float2 x0 = src[P(rb)];
        const float2 x1 = src[P(rb + s_ * mq)];
        const float2 x2 = src[P(rb + s_ * 2 * mq)];
        const float2 x3 = src[P(rb + s_ * 3 * mq)];

        const float2 va = make_float2(x0.x + x2.x, x0.y + x2.y);
        const float2 vb = make_float2(x0.x - x2.x, x0.y - x2.y);
        const float2 vc = make_float2(x1.x + x3.x, x1.y + x3.y);
        const float2 vd = make_float2(x1.x - x3.x, x1.y - x3.y);

        const float2 y0 = make_float2(va.x + vc.x, va.y + vc.y);
        const float2 y1 = make_float2(vb.x - vd.y, vb.y + vd.x);   // b + i d
        const float2 y2 = make_float2(va.x - vc.x, va.y - vc.y);
        const float2 y3 = make_float2(vb.x + vd.y, vb.y - vd.x);   // b - i d

        const float2 w1 = tw4[(p)     << ls];
        const float2 w2 = tw4[(2 * p) << ls];
        const float2 w3 = tw4[(3 * p) << ls];

        const int wb = q + s_ * 4 * p;
        dst[P(wb)]          = y0;
        dst[P(wb + s_)]     = cmul(w1, y1);
        dst[P(wb + 2 * s_)] = cmul(w2, y2);
        dst[P(wb + 3 * s_)] = cmul(w3, y3);

        float2* t = src; src = dst; dst = t;
        s_ <<= 2; ls += 2;
    }
    __syncthreads();

    // result in src; z[j] = x[2j] + i*x[2j+1]
    float4* o4 = (float4*)(out + (size_t)h * LEN);
    #pragma unroll
    for (int r = 0; r < 2; r++) {
        const int j = tid + r * 256;
        const float2 z0 = src[P(2 * j)];
        const float2 z1 = src[P(2 * j + 1)];
        o4[j] = make_float4(z0.x, z0.y, z1.x, z1.y);
    }
}

extern "C" void kernel_launch(void* const* d_in, const int* in_sizes, int n_in,
                              void* d_out, int out_size)
{
    const float* log_dt     = (const float*)d_in[0];
    const float* log_w_real = (const float*)d_in[1];
    const float* w_imag     = (const float*)d_in[2];
    const float* Bmat       = (const float*)d_in[3];
    const float* Cmat       = (const float*)d_in[4];
    const float* Pmat       = (const float*)d_in[5];
    float* out = (float*)d_out;

    dim3 g1(HDIM, 4);
    cauchy_kernel<<<g1, 256>>>(log_dt, log_w_real, w_imag, Bmat, Cmat, Pmat);
    irfft_kernel<<<HDIM, 256>>>(out);
}